// round 15
// baseline (speedup 1.0000x reference)
#include <cuda_runtime.h>
#include <cstdint>

#define T_SEQ 32768
#define HID   512
#define CS    16       // cluster size per direction (nonportable, 2 clusters)
#define NTHR  256      // threads per scan CTA

// 64 MB scratch for xp = x @ Wx^T + b  (device global: allowed, no runtime alloc)
__device__ float g_xp[(size_t)T_SEQ * HID];

// ---------------------------------------------------------------------------
// Kernel 1: xp[m,n] = sum_k x[m,k] * Wx[n,k] + b[n]
// (also serves as the clock canary: ~411us at normal clock)
// ---------------------------------------------------------------------------
#define BM 128
#define BN 128
#define BK 16

__global__ void __launch_bounds__(256) gemm_xp_kernel(
    const float* __restrict__ x, const float* __restrict__ Wx,
    const float* __restrict__ b)
{
    __shared__ float As[BK][BM + 4];
    __shared__ float Bs[BK][BN + 4];
    const int bm  = blockIdx.y * BM;
    const int bn  = blockIdx.x * BN;
    const int tid = threadIdx.x;
    const int tx  = tid & 15;
    const int ty  = tid >> 4;

    float acc[8][8];
#pragma unroll
    for (int i = 0; i < 8; i++)
#pragma unroll
        for (int j = 0; j < 8; j++) acc[i][j] = 0.f;

    for (int k0 = 0; k0 < HID; k0 += BK) {
#pragma unroll
        for (int i = 0; i < 2; i++) {
            int idx = tid * 2 + i;
            int r   = idx >> 2;
            int c4  = (idx & 3) * 4;
            float4 va = *(const float4*)&x [(size_t)(bm + r) * HID + k0 + c4];
            As[c4 + 0][r] = va.x; As[c4 + 1][r] = va.y;
            As[c4 + 2][r] = va.z; As[c4 + 3][r] = va.w;
            float4 vb = *(const float4*)&Wx[(size_t)(bn + r) * HID + k0 + c4];
            Bs[c4 + 0][r] = vb.x; Bs[c4 + 1][r] = vb.y;
            Bs[c4 + 2][r] = vb.z; Bs[c4 + 3][r] = vb.w;
        }
        __syncthreads();
#pragma unroll
        for (int k = 0; k < BK; k++) {
            float a[8], bb[8];
#pragma unroll
            for (int i = 0; i < 8; i++) a[i]  = As[k][ty * 8 + i];
#pragma unroll
            for (int j = 0; j < 8; j++) bb[j] = Bs[k][tx * 8 + j];
#pragma unroll
            for (int i = 0; i < 8; i++)
#pragma unroll
                for (int j = 0; j < 8; j++)
                    acc[i][j] = fmaf(a[i], bb[j], acc[i][j]);
        }
        __syncthreads();
    }

#pragma unroll
    for (int i = 0; i < 8; i++) {
        int m = bm + ty * 8 + i;
#pragma unroll
        for (int j = 0; j < 8; j += 4) {
            int n = bn + tx * 8 + j;
            float4 v;
            v.x = acc[i][j + 0] + b[n + 0];
            v.y = acc[i][j + 1] + b[n + 1];
            v.z = acc[i][j + 2] + b[n + 2];
            v.w = acc[i][j + 3] + b[n + 3];
            *(float4*)&g_xp[(size_t)m * HID + n] = v;
        }
    }
}

// ---------------------------------------------------------------------------
// Kernel 2: recurrent scans. 2 clusters x 16 CTAs x 256 threads.
// R15: 2-rows-per-thread layout halves smem crossbar traffic (512 -> 256
// wavefronts per CTA per step). Thread (g = tid>>4, c = tid&15) owns rows
// {rk*32+2g, +1} x cols [32c, 32c+32). h layout: word = col + 2*(col/32)
// (chunk stride 34 words = 136 B -> 8B-aligned, banks {2c,2c+1} tile all 32
// banks conflict-free). h loads are 8B (ld.shared.b64) -- 16B loads would be
// misaligned for odd c (the R14 crash). Protocol (mbarriers, expect_tx,
// 512 x 4B st.async msgs) byte-identical to R5.
// ---------------------------------------------------------------------------
__device__ __forceinline__ uint32_t smem_u32(const void* p) {
    uint32_t a;
    asm("{ .reg .u64 t; cvta.to.shared.u64 t, %1; cvt.u32.u64 %0, t; }"
        : "=r"(a) : "l"(p));
    return a;
}

#define MBAR_INIT(addr, cnt) \
    asm volatile("mbarrier.init.shared.b64 [%0], %1;" :: "r"(addr), "r"(cnt) : "memory")

#define MBAR_ARRIVE_EXPECT_TX(addr, tx) \
    asm volatile("mbarrier.arrive.expect_tx.shared.b64 _, [%0], %1;" \
                 :: "r"(addr), "r"(tx) : "memory")

#define MBAR_WAIT(addr, ph) do {                                               \
    uint32_t _done;                                                            \
    asm volatile("{\n\t.reg .pred p;\n\t"                                      \
        "mbarrier.try_wait.parity.acquire.cta.shared::cta.b64 p, [%1], %2;\n\t"\
        "selp.b32 %0, 1, 0, p;\n\t}"                                           \
        : "=r"(_done) : "r"(addr), "r"(ph) : "memory");                        \
    if (!_done) {                                                              \
        asm volatile("{\n\t.reg .pred P1;\n\t"                                 \
            "WL_%=:\n\t"                                                       \
            "mbarrier.try_wait.parity.acquire.cta.shared::cta.b64 P1, [%0], %1, 0x989680;\n\t" \
            "@P1 bra.uni WD_%=;\n\t"                                           \
            "bra.uni WL_%=;\n\t"                                               \
            "WD_%=:\n\t}"                                                      \
            :: "r"(addr), "r"(ph) : "memory");                                 \
    }                                                                          \
} while (0)

#define HPAD 544   // 16 chunks * 34 words: word = col + 2*(col/32)

__global__ void __launch_bounds__(NTHR, 1)
scan_kernel(const float* __restrict__ Wh, float* __restrict__ out)
{
    __shared__ alignas(16) float hs[2][HPAD];
    __shared__ alignas(8) unsigned long long mbar[2];

    const int tid = threadIdx.x;
    const int dir = blockIdx.x / CS;     // 0 = forward, 1 = reverse
    const int rk  = blockIdx.x % CS;     // cluster rank
    const int g   = tid >> 4;            // 0..15 row-pair group
    const int c   = tid & 15;            // 0..15 (32-col chunk)
    const int r0  = rk * 32 + 2 * g;     // first of my two rows
    const int rsend = r0 + (tid & 1);    // row I publish (senders: c<2)

    // ---- weights for 2 rows x 32 cols, as f32x2 pairs (32 x 8B regs) ----
    unsigned long long wA[16], wB[16];   // wA: row r0, wB: row r0+1
    {
        const ulonglong2* w0 =
            (const ulonglong2*)&Wh[(size_t)r0 * HID + c * 32];
        const ulonglong2* w1 =
            (const ulonglong2*)&Wh[(size_t)(r0 + 1) * HID + c * 32];
#pragma unroll
        for (int i = 0; i < 8; i++) {
            ulonglong2 v0 = w0[i];
            wA[2 * i] = v0.x; wA[2 * i + 1] = v0.y;
            ulonglong2 v1 = w1[i];
            wB[2 * i] = v1.x; wB[2 * i + 1] = v1.y;
        }
    }

    // ---- zero both h buffers (h0 = 0) ----
    for (int i = tid; i < 2 * HPAD; i += NTHR) ((float*)hs)[i] = 0.f;

    const uint32_t buf0  = smem_u32(&hs[0][0]);
    const uint32_t mb    = smem_u32(&mbar[0]);
    const uint32_t mbrel = mb - buf0;    // mbar offset relative to hs base

    // DSMEM addressing is linear in local offset -> one mapa per rank serves
    // both buffers and both mbarriers.
    uint32_t rank_base[CS];
#pragma unroll
    for (int r = 0; r < CS; r++) {
        asm("mapa.shared::cluster.u32 %0, %1, %2;"
            : "=r"(rank_base[r]) : "r"(buf0), "r"(r));
    }

    if (tid == 0) {
        MBAR_INIT(mb,     1u);
        MBAR_INIT(mb + 8, 1u);
        // pre-arm both phases' arrivals + tx expectations (512 msgs x 4B)
        MBAR_ARRIVE_EXPECT_TX(mb,     2048u);
        MBAR_ARRIVE_EXPECT_TX(mb + 8, 2048u);
    }
    __syncthreads();
    // all CTAs: buffers zeroed + mbars armed before any remote st.async
    asm volatile("barrier.cluster.arrive.aligned;" ::: "memory");
    asm volatile("barrier.cluster.wait.aligned;"   ::: "memory");

    float* out_h = out + 512 + (size_t)dir * T_SEQ * HID;

    // destination word for my published h value: col j = rsend ->
    // word = j + 2*(j/32) = 34*rk + (2g + (tid&1))
    const uint32_t doff0 =
        (uint32_t)(34 * rk + 2 * g + (tid & 1)) * 4u;
    const uint32_t doff1 = doff0 + (uint32_t)HPAD * 4u;

    // my h-read base: chunk c -> word 34*c (byte 136*c, 8B-aligned)
    const int hbase = 34 * c;

    // ---- xp software pipeline (depth 2), for my publish row ----
    float xp0, xp1;
    {
        size_t i0 = (size_t)(dir ? (T_SEQ - 1) : 0) * HID + rsend;
        size_t i1 = (size_t)(dir ? (T_SEQ - 2) : 1) * HID + rsend;
        xp0 = g_xp[i0];
        xp1 = g_xp[i1];
    }

    int ph0 = 0, ph1 = 0;

    for (int t = 0; t < T_SEQ; t++) {
        float xpn = 0.f;
        if (t + 2 < T_SEQ) {
            size_t ii = (size_t)(dir ? (T_SEQ - 3 - t) : (t + 2)) * HID + rsend;
            xpn = __ldg(&g_xp[ii]);
        }

        const int cur = t & 1;
        if (t > 0) {
            if (cur) {
                MBAR_WAIT(mb + 8, ph1); ph1 ^= 1;
                // re-arm this mbar for its next phase (t+2 data). Early peer
                // tx are absorbed (tx-count may go transiently negative).
                if (tid == 0 && t + 2 < T_SEQ)
                    MBAR_ARRIVE_EXPECT_TX(mb + 8, 2048u);
            } else {
                MBAR_WAIT(mb, ph0); ph0 ^= 1;
                if (tid == 0 && t + 2 < T_SEQ)
                    MBAR_ARRIVE_EXPECT_TX(mb, 2048u);
            }
        }

        // ---- dual-row matvec: 32 cols, each 8B h-load feeds 2 rows ----
        const float* hp = &hs[cur][hbase];
        unsigned long long A0 = 0ull, A1 = 0ull, B0 = 0ull, B1 = 0ull;
#pragma unroll
        for (int j = 0; j < 8; j++) {
            unsigned long long h0 =
                *(const unsigned long long*)(hp + 4 * j);      // cols 4j..4j+1
            unsigned long long h1 =
                *(const unsigned long long*)(hp + 4 * j + 2);  // cols 4j+2..3
            asm("fma.rn.f32x2 %0, %1, %2, %3;"
                : "=l"(A0) : "l"(wA[2 * j]),     "l"(h0), "l"(A0));
            asm("fma.rn.f32x2 %0, %1, %2, %3;"
                : "=l"(A1) : "l"(wA[2 * j + 1]), "l"(h1), "l"(A1));
            asm("fma.rn.f32x2 %0, %1, %2, %3;"
                : "=l"(B0) : "l"(wB[2 * j]),     "l"(h0), "l"(B0));
            asm("fma.rn.f32x2 %0, %1, %2, %3;"
                : "=l"(B1) : "l"(wB[2 * j + 1]), "l"(h1), "l"(B1));
        }
        unsigned long long sAp, sBp;
        asm("add.rn.f32x2 %0, %1, %2;" : "=l"(sAp) : "l"(A0), "l"(A1));
        asm("add.rn.f32x2 %0, %1, %2;" : "=l"(sBp) : "l"(B0), "l"(B1));
        uint32_t alo, ahi, blo, bhi;
        asm("mov.b64 {%0,%1}, %2;" : "=r"(alo), "=r"(ahi) : "l"(sAp));
        asm("mov.b64 {%0,%1}, %2;" : "=r"(blo), "=r"(bhi) : "l"(sBp));
        float s0 = __uint_as_float(alo) + __uint_as_float(ahi);  // row r0
        float s1 = __uint_as_float(blo) + __uint_as_float(bhi);  // row r0+1

        // reduce across the 16 chunk-lanes of this row group (both rows)
        s0 += __shfl_xor_sync(0xffffffffu, s0, 1);
        s1 += __shfl_xor_sync(0xffffffffu, s1, 1);
        s0 += __shfl_xor_sync(0xffffffffu, s0, 2);
        s1 += __shfl_xor_sync(0xffffffffu, s1, 2);
        s0 += __shfl_xor_sync(0xffffffffu, s0, 4);
        s1 += __shfl_xor_sync(0xffffffffu, s1, 4);
        s0 += __shfl_xor_sync(0xffffffffu, s0, 8);
        s1 += __shfl_xor_sync(0xffffffffu, s1, 8);

        float z = ((tid & 1) ? s1 : s0) + xp0;
        // fast accurate tanh: h = 1 - 2/(exp(2z)+1), via ex2/rcp MUFU
        float e, r;
        asm("ex2.approx.f32 %0, %1;" : "=f"(e) : "f"(z * 2.885390082f));
        asm("rcp.approx.f32 %0, %1;" : "=f"(r) : "f"(e + 1.0f));
        float h = fmaf(-2.0f, r, 1.0f);

        if (c < 2) {   // senders: lanes c==0 (row r0) and c==1 (row r0+1)
            if (t + 1 < T_SEQ) {
                // publish h to every rank's next-phase buffer (incl. self)
                const uint32_t doff = cur ? doff0 : doff1;   // dest buf = cur^1
                const uint32_t moff = mbrel + (cur ? 0u : 8u);
#pragma unroll
                for (int pr = 0; pr < CS; pr++) {
                    asm volatile(
                        "st.async.weak.shared::cluster.mbarrier::complete_tx::bytes.f32 "
                        "[%0], %1, [%2];"
                        :: "r"(rank_base[pr] + doff), "f"(h),
                           "r"(rank_base[pr] + moff) : "memory");
                }
            }
            // store the history AFTER the sends (off the critical path)
            out_h[(size_t)t * HID + rsend] = h;
        }

        xp0 = xp1;
        xp1 = xpn;
    }
}

// ---------------------------------------------------------------------------
// Kernel 3: y = Wout @ concat(h_fwd[-1], h_rev[-1]) + bout   (unchanged)
// ---------------------------------------------------------------------------
__global__ void __launch_bounds__(256) readout_kernel(
    const float* __restrict__ Wout, const float* __restrict__ bout,
    float* __restrict__ out)
{
    const int j = blockIdx.x;
    const float* hf = out + 512 + (size_t)(T_SEQ - 1) * HID;
    const float* hr = out + 512 + (size_t)T_SEQ * HID + (size_t)(T_SEQ - 1) * HID;
    const float* wr = Wout + (size_t)j * (2 * HID);

    float s = 0.f;
    for (int i = threadIdx.x; i < HID; i += 256) s = fmaf(wr[i],       hf[i], s);
    for (int i = threadIdx.x; i < HID; i += 256) s = fmaf(wr[HID + i], hr[i], s);

#pragma unroll
    for (int o = 16; o > 0; o >>= 1) s += __shfl_xor_sync(0xffffffffu, s, o);

    __shared__ float red[8];
    if ((threadIdx.x & 31) == 0) red[threadIdx.x >> 5] = s;
    __syncthreads();
    if (threadIdx.x == 0) {
        float tot = 0.f;
#pragma unroll
        for (int i = 0; i < 8; i++) tot += red[i];
        out[j] = tot + bout[j];
    }
}

// ---------------------------------------------------------------------------
extern "C" void kernel_launch(void* const* d_in, const int* in_sizes, int n_in,
                              void* d_out, int out_size)
{
    const float* x    = (const float*)d_in[0];
    const float* Wx   = (const float*)d_in[1];
    const float* Wh   = (const float*)d_in[2];
    const float* b    = (const float*)d_in[3];
    const float* Wout = (const float*)d_in[4];
    const float* bout = (const float*)d_in[5];
    float* out = (float*)d_out;

    dim3 ggrid(HID / BN, T_SEQ / BM);           // (4, 256)
    gemm_xp_kernel<<<ggrid, 256>>>(x, Wx, b);

    // 2 clusters of 16 CTAs (nonportable cluster size)
    cudaFuncSetAttribute(scan_kernel,
                         cudaFuncAttributeNonPortableClusterSizeAllowed, 1);
    cudaLaunchConfig_t cfg = {};
    cfg.gridDim  = dim3(2 * CS, 1, 1);
    cfg.blockDim = dim3(NTHR, 1, 1);
    cfg.dynamicSmemBytes = 0;
    cfg.stream = 0;
    cudaLaunchAttribute attrs[1];
    attrs[0].id = cudaLaunchAttributeClusterDimension;
    attrs[0].val.clusterDim = {CS, 1, 1};
    cfg.attrs = attrs;
    cfg.numAttrs = 1;
    cudaLaunchKernelEx(&cfg, scan_kernel, Wh, out);

    readout_kernel<<<HID, 256>>>(Wout, bout, out);
}

// round 16
// speedup vs baseline: 1.0466x; 1.0466x over previous
#include <cuda_runtime.h>
#include <cstdint>

#define T_SEQ 32768
#define HID   512
#define CS    16       // cluster size per direction (nonportable, 2 clusters)
#define NTHR  256      // threads per scan CTA

// 64 MB scratch for xp = x @ Wx^T + b  (device global: allowed, no runtime alloc)
__device__ float g_xp[(size_t)T_SEQ * HID];

// ---------------------------------------------------------------------------
// Kernel 1: xp[m,n] = sum_k x[m,k] * Wx[n,k] + b[n]
// (also serves as the clock canary: ~411us at normal clock)
// ---------------------------------------------------------------------------
#define BM 128
#define BN 128
#define BK 16

__global__ void __launch_bounds__(256) gemm_xp_kernel(
    const float* __restrict__ x, const float* __restrict__ Wx,
    const float* __restrict__ b)
{
    __shared__ float As[BK][BM + 4];
    __shared__ float Bs[BK][BN + 4];
    const int bm  = blockIdx.y * BM;
    const int bn  = blockIdx.x * BN;
    const int tid = threadIdx.x;
    const int tx  = tid & 15;
    const int ty  = tid >> 4;

    float acc[8][8];
#pragma unroll
    for (int i = 0; i < 8; i++)
#pragma unroll
        for (int j = 0; j < 8; j++) acc[i][j] = 0.f;

    for (int k0 = 0; k0 < HID; k0 += BK) {
#pragma unroll
        for (int i = 0; i < 2; i++) {
            int idx = tid * 2 + i;
            int r   = idx >> 2;
            int c4  = (idx & 3) * 4;
            float4 va = *(const float4*)&x [(size_t)(bm + r) * HID + k0 + c4];
            As[c4 + 0][r] = va.x; As[c4 + 1][r] = va.y;
            As[c4 + 2][r] = va.z; As[c4 + 3][r] = va.w;
            float4 vb = *(const float4*)&Wx[(size_t)(bn + r) * HID + k0 + c4];
            Bs[c4 + 0][r] = vb.x; Bs[c4 + 1][r] = vb.y;
            Bs[c4 + 2][r] = vb.z; Bs[c4 + 3][r] = vb.w;
        }
        __syncthreads();
#pragma unroll
        for (int k = 0; k < BK; k++) {
            float a[8], bb[8];
#pragma unroll
            for (int i = 0; i < 8; i++) a[i]  = As[k][ty * 8 + i];
#pragma unroll
            for (int j = 0; j < 8; j++) bb[j] = Bs[k][tx * 8 + j];
#pragma unroll
            for (int i = 0; i < 8; i++)
#pragma unroll
                for (int j = 0; j < 8; j++)
                    acc[i][j] = fmaf(a[i], bb[j], acc[i][j]);
        }
        __syncthreads();
    }

#pragma unroll
    for (int i = 0; i < 8; i++) {
        int m = bm + ty * 8 + i;
#pragma unroll
        for (int j = 0; j < 8; j += 4) {
            int n = bn + tx * 8 + j;
            float4 v;
            v.x = acc[i][j + 0] + b[n + 0];
            v.y = acc[i][j + 1] + b[n + 1];
            v.z = acc[i][j + 2] + b[n + 2];
            v.w = acc[i][j + 3] + b[n + 3];
            *(float4*)&g_xp[(size_t)m * HID + n] = v;
        }
    }
}

// ---------------------------------------------------------------------------
// Kernel 2: recurrent scans. 2 clusters x 16 CTAs x 256 threads.
// EXACT R5 protocol and body -- the measured optimum. Each CTA owns 32 rows;
// thread (row_local, sub) handles row rk*32+row_local, cols [64*sub,+64).
// Ping-pong global mbarriers (warp-uniform wait addresses); publish = 16x 4B
// st.async burst from each sub==0 lane, signaling receivers' mbars via
// complete_tx::bytes. Nine structural/micro variants tested (R6-R9, R13-R15)
// all measured neutral-or-worse: the step is a serial recurrence-latency
// floor (mbar wake + LDS + chain + DSMEM fabric flight + straggler spread).
// ---------------------------------------------------------------------------
__device__ __forceinline__ uint32_t smem_u32(const void* p) {
    uint32_t a;
    asm("{ .reg .u64 t; cvta.to.shared.u64 t, %1; cvt.u32.u64 %0, t; }"
        : "=r"(a) : "l"(p));
    return a;
}

#define MBAR_INIT(addr, cnt) \
    asm volatile("mbarrier.init.shared.b64 [%0], %1;" :: "r"(addr), "r"(cnt) : "memory")

#define MBAR_ARRIVE_EXPECT_TX(addr, tx) \
    asm volatile("mbarrier.arrive.expect_tx.shared.b64 _, [%0], %1;" \
                 :: "r"(addr), "r"(tx) : "memory")

#define MBAR_WAIT(addr, ph) do {                                               \
    uint32_t _done;                                                            \
    asm volatile("{\n\t.reg .pred p;\n\t"                                      \
        "mbarrier.try_wait.parity.acquire.cta.shared::cta.b64 p, [%1], %2;\n\t"\
        "selp.b32 %0, 1, 0, p;\n\t}"                                           \
        : "=r"(_done) : "r"(addr), "r"(ph) : "memory");                        \
    if (!_done) {                                                              \
        asm volatile("{\n\t.reg .pred P1;\n\t"                                 \
            "WL_%=:\n\t"                                                       \
            "mbarrier.try_wait.parity.acquire.cta.shared::cta.b64 P1, [%0], %1, 0x989680;\n\t" \
            "@P1 bra.uni WD_%=;\n\t"                                           \
            "bra.uni WL_%=;\n\t"                                               \
            "WD_%=:\n\t}"                                                      \
            :: "r"(addr), "r"(ph) : "memory");                                 \
    }                                                                          \
} while (0)

#define HPAD 544   // 8 chunks * 68 words: word = col + 4*(col/64), conflict-free

__global__ void __launch_bounds__(NTHR, 1)
scan_kernel(const float* __restrict__ Wh, float* __restrict__ out)
{
    __shared__ alignas(16) float hs[2][HPAD];
    __shared__ alignas(8) unsigned long long mbar[2];

    const int tid       = threadIdx.x;
    const int dir       = blockIdx.x / CS;   // 0 = forward, 1 = reverse
    const int rk        = blockIdx.x % CS;   // cluster rank
    const int row_local = tid >> 3;          // 0..31
    const int sub       = tid & 7;           // 0..7 (64-col chunk)
    const int row       = rk * 32 + row_local;

    // ---- weights into registers as f32x2 pairs: 4 independent chains ----
    unsigned long long w2[32];
    {
        const ulonglong2* wp =
            (const ulonglong2*)&Wh[(size_t)row * HID + sub * 64];
#pragma unroll
        for (int i = 0; i < 16; i++) {
            ulonglong2 v = wp[i];
            w2[2 * i]     = v.x;
            w2[2 * i + 1] = v.y;
        }
    }

    // ---- zero both h buffers (h0 = 0) ----
    for (int i = tid; i < 2 * HPAD; i += NTHR) ((float*)hs)[i] = 0.f;

    const uint32_t buf0  = smem_u32(&hs[0][0]);
    const uint32_t mb    = smem_u32(&mbar[0]);
    const uint32_t mbrel = mb - buf0;        // mbar offset relative to hs base

    // DSMEM addressing is linear in local offset -> one mapa per rank serves
    // both buffers and both mbarriers.
    uint32_t rank_base[CS];
#pragma unroll
    for (int r = 0; r < CS; r++) {
        asm("mapa.shared::cluster.u32 %0, %1, %2;"
            : "=r"(rank_base[r]) : "r"(buf0), "r"(r));
    }

    if (tid == 0) {
        MBAR_INIT(mb,     1u);
        MBAR_INIT(mb + 8, 1u);
        // pre-arm both phases' arrivals + tx expectations (512 msgs x 4B)
        MBAR_ARRIVE_EXPECT_TX(mb,     2048u);
        MBAR_ARRIVE_EXPECT_TX(mb + 8, 2048u);
    }
    __syncthreads();
    // all CTAs: buffers zeroed + mbars armed before any remote st.async
    asm volatile("barrier.cluster.arrive.aligned;" ::: "memory");
    asm volatile("barrier.cluster.wait.aligned;"   ::: "memory");

    float* out_h = out + 512 + (size_t)dir * T_SEQ * HID;

    // destination offsets for my h value: global row = rk*32+row_local sits in
    // 64-col chunk (rk>>1), word 68*(rk>>1) + 32*(rk&1) + row_local.
    const uint32_t doff0 =
        (uint32_t)(68 * (rk >> 1) + 32 * (rk & 1) + row_local) * 4u;
    const uint32_t doff1 = doff0 + (uint32_t)HPAD * 4u;

    // ---- xp software pipeline (depth 2) ----
    float xp0, xp1;
    {
        size_t i0 = (size_t)(dir ? (T_SEQ - 1) : 0) * HID + row;
        size_t i1 = (size_t)(dir ? (T_SEQ - 2) : 1) * HID + row;
        xp0 = g_xp[i0];
        xp1 = g_xp[i1];
    }

    int ph0 = 0, ph1 = 0;

    for (int t = 0; t < T_SEQ; t++) {
        float xpn = 0.f;
        if (t + 2 < T_SEQ) {
            size_t ii = (size_t)(dir ? (T_SEQ - 3 - t) : (t + 2)) * HID + row;
            xpn = __ldg(&g_xp[ii]);
        }

        const int cur = t & 1;
        if (t > 0) {
            if (cur) {
                MBAR_WAIT(mb + 8, ph1); ph1 ^= 1;
                // re-arm this mbar for its next phase (t+2 data). Early peer
                // tx are absorbed (tx-count may go transiently negative).
                if (tid == 0 && t + 2 < T_SEQ)
                    MBAR_ARRIVE_EXPECT_TX(mb + 8, 2048u);
            } else {
                MBAR_WAIT(mb, ph0); ph0 ^= 1;
                if (tid == 0 && t + 2 < T_SEQ)
                    MBAR_ARRIVE_EXPECT_TX(mb, 2048u);
            }
        }

        // ---- partial matvec: 64 cols, 4 independent f32x2 FMA chains ----
        const float* hp = &hs[cur][68 * sub];
        unsigned long long a0 = 0ull, a1 = 0ull, a2 = 0ull, a3 = 0ull;
#pragma unroll
        for (int k = 0; k < 8; k++) {
            ulonglong2 hA = *(const ulonglong2*)(hp + 8 * k);
            ulonglong2 hB = *(const ulonglong2*)(hp + 8 * k + 4);
            asm("fma.rn.f32x2 %0, %1, %2, %3;"
                : "=l"(a0) : "l"(w2[4 * k + 0]), "l"(hA.x), "l"(a0));
            asm("fma.rn.f32x2 %0, %1, %2, %3;"
                : "=l"(a1) : "l"(w2[4 * k + 1]), "l"(hA.y), "l"(a1));
            asm("fma.rn.f32x2 %0, %1, %2, %3;"
                : "=l"(a2) : "l"(w2[4 * k + 2]), "l"(hB.x), "l"(a2));
            asm("fma.rn.f32x2 %0, %1, %2, %3;"
                : "=l"(a3) : "l"(w2[4 * k + 3]), "l"(hB.y), "l"(a3));
        }
        // pairwise f32x2 combine: 3 packed adds + 1 unpack + 1 add
        unsigned long long s01, s23, sAll;
        asm("add.rn.f32x2 %0, %1, %2;" : "=l"(s01)  : "l"(a0),  "l"(a1));
        asm("add.rn.f32x2 %0, %1, %2;" : "=l"(s23)  : "l"(a2),  "l"(a3));
        asm("add.rn.f32x2 %0, %1, %2;" : "=l"(sAll) : "l"(s01), "l"(s23));
        uint32_t slo, shi;
        asm("mov.b64 {%0,%1}, %2;" : "=r"(slo), "=r"(shi) : "l"(sAll));
        float s = __uint_as_float(slo) + __uint_as_float(shi);

        // reduce across the 8 sub-threads of this row
        s += __shfl_xor_sync(0xffffffffu, s, 1);
        s += __shfl_xor_sync(0xffffffffu, s, 2);
        s += __shfl_xor_sync(0xffffffffu, s, 4);

        float z = s + xp0;
        // fast accurate tanh: h = 1 - 2/(exp(2z)+1), via ex2/rcp MUFU
        float e, r;
        asm("ex2.approx.f32 %0, %1;" : "=f"(e) : "f"(z * 2.885390082f));
        asm("rcp.approx.f32 %0, %1;" : "=f"(r) : "f"(e + 1.0f));
        float h = fmaf(-2.0f, r, 1.0f);

        if (sub == 0) {
            if (t + 1 < T_SEQ) {
                // publish h to every rank's next-phase buffer (incl. self)
                const uint32_t doff = cur ? doff0 : doff1;   // dest buf = cur^1
                const uint32_t moff = mbrel + (cur ? 0u : 8u);
#pragma unroll
                for (int pr = 0; pr < CS; pr++) {
                    asm volatile(
                        "st.async.weak.shared::cluster.mbarrier::complete_tx::bytes.f32 "
                        "[%0], %1, [%2];"
                        :: "r"(rank_base[pr] + doff), "f"(h),
                           "r"(rank_base[pr] + moff) : "memory");
                }
            }
            out_h[(size_t)t * HID + row] = h;
        }

        xp0 = xp1;
        xp1 = xpn;
    }
}

// ---------------------------------------------------------------------------
// Kernel 3: y = Wout @ concat(h_fwd[-1], h_rev[-1]) + bout   (unchanged)
// ---------------------------------------------------------------------------
__global__ void __launch_bounds__(256) readout_kernel(
    const float* __restrict__ Wout, const float* __restrict__ bout,
    float* __restrict__ out)
{
    const int j = blockIdx.x;
    const float* hf = out + 512 + (size_t)(T_SEQ - 1) * HID;
    const float* hr = out + 512 + (size_t)T_SEQ * HID + (size_t)(T_SEQ - 1) * HID;
    const float* wr = Wout + (size_t)j * (2 * HID);

    float s = 0.f;
    for (int i = threadIdx.x; i < HID; i += 256) s = fmaf(wr[i],       hf[i], s);
    for (int i = threadIdx.x; i < HID; i += 256) s = fmaf(wr[HID + i], hr[i], s);

#pragma unroll
    for (int o = 16; o > 0; o >>= 1) s += __shfl_xor_sync(0xffffffffu, s, o);

    __shared__ float red[8];
    if ((threadIdx.x & 31) == 0) red[threadIdx.x >> 5] = s;
    __syncthreads();
    if (threadIdx.x == 0) {
        float tot = 0.f;
#pragma unroll
        for (int i = 0; i < 8; i++) tot += red[i];
        out[j] = tot + bout[j];
    }
}

// ---------------------------------------------------------------------------
extern "C" void kernel_launch(void* const* d_in, const int* in_sizes, int n_in,
                              void* d_out, int out_size)
{
    const float* x    = (const float*)d_in[0];
    const float* Wx   = (const float*)d_in[1];
    const float* Wh   = (const float*)d_in[2];
    const float* b    = (const float*)d_in[3];
    const float* Wout = (const float*)d_in[4];
    const float* bout = (const float*)d_in[5];
    float* out = (float*)d_out;

    dim3 ggrid(HID / BN, T_SEQ / BM);           // (4, 256)
    gemm_xp_kernel<<<ggrid, 256>>>(x, Wx, b);

    // 2 clusters of 16 CTAs (nonportable cluster size)
    cudaFuncSetAttribute(scan_kernel,
                         cudaFuncAttributeNonPortableClusterSizeAllowed, 1);
    cudaLaunchConfig_t cfg = {};
    cfg.gridDim  = dim3(2 * CS, 1, 1);
    cfg.blockDim = dim3(NTHR, 1, 1);
    cfg.dynamicSmemBytes = 0;
    cfg.stream = 0;
    cudaLaunchAttribute attrs[1];
    attrs[0].id = cudaLaunchAttributeClusterDimension;
    attrs[0].val.clusterDim = {CS, 1, 1};
    cfg.attrs = attrs;
    cfg.numAttrs = 1;
    cudaLaunchKernelEx(&cfg, scan_kernel, Wh, out);

    readout_kernel<<<HID, 256>>>(Wout, bout, out);
}